// round 12
// baseline (speedup 1.0000x reference)
#include <cuda_runtime.h>
#include <cuda_fp16.h>
#include <cstdint>

// Problem constants
#define B_DIM 4096
#define E_DIM 1024
#define O_DIM 16
#define H_DIM 1024
#define KOH   (O_DIM * H_DIM)
#define KPE   512                        // k-pairs per full K (1024/2)

// Tiling
#define TM 128
#define TN 128
#define KPC 16                           // k-pairs per chunk (32 floats)
#define NCHUNK (KPE / KPC)               // 32
#define NTHREADS 256
#define MAX_TILES (B_DIM / TM + O_DIM)   // 48

// smem (u32 units). A: [m][kp] pitch 20 (banks 20g+tig all-distinct);
// B: [kp][n] pitch 136 (banks 8tig+8nt+g all-distinct). Both cp.async-filled.
#define APITCH 20
#define BPITCH 136
#define A_TILE (TM * APITCH)             // 2560
#define B_TILE (KPC * BPITCH)            // 2176
#define ST_AH 0
#define ST_AL A_TILE
#define ST_BH (2 * A_TILE)               // 5120
#define ST_BL (2 * A_TILE + B_TILE)      // 7296
#define STAGE_U32 (2 * A_TILE + 2 * B_TILE)   // 9472
#define STAGE_BYTES (STAGE_U32 * 4)           // 37888
#define NSTAGE 3
#define SMEM_NEED (NSTAGE * STAGE_BYTES)      // 113664 (x2 CTAs = 227KB <= 228KB/SM)

// ---- device scratch (allocation-free __device__ globals) ----
__device__ int      g_perm[B_DIM];
__device__ int      g_tile_op[MAX_TILES];
__device__ int      g_tile_start[MAX_TILES];
__device__ int      g_tile_rows[MAX_TILES];
__device__ int      g_num_tiles;
__device__ uint32_t g_w1h[(size_t)O_DIM * KPE * H_DIM];   // [o][kp][n] packed half2
__device__ uint32_t g_w1l[(size_t)O_DIM * KPE * H_DIM];
__device__ uint32_t g_w2h[(size_t)O_DIM * KPE * H_DIM];
__device__ uint32_t g_w2l[(size_t)O_DIM * KPE * H_DIM];
__device__ uint32_t g_xh[(size_t)B_DIM * KPE];            // [b][kp]
__device__ uint32_t g_xl[(size_t)B_DIM * KPE];
__device__ uint32_t g_h1h[(size_t)B_DIM * KPE];           // [permuted row][kp]
__device__ uint32_t g_h1l[(size_t)B_DIM * KPE];

// ============================================================================
// Helpers — baseline PTX only (cp.async + mma.sync m16n8k16, both sm_80+)
// ============================================================================
__device__ __forceinline__ uint32_t smem_u32(const void* p) {
    uint32_t a;
    asm("{ .reg .u64 t; cvta.to.shared.u64 t, %1; cvt.u32.u64 %0, t; }"
        : "=r"(a) : "l"(p));
    return a;
}
__device__ __forceinline__ void cp_async16(uint32_t dst, const void* src) {
    asm volatile("cp.async.ca.shared.global [%0], [%1], 16;" :: "r"(dst), "l"(src));
}
__device__ __forceinline__ void cp_commit() {
    asm volatile("cp.async.commit_group;" ::: "memory");
}
template <int N>
__device__ __forceinline__ void cp_wait() {
    asm volatile("cp.async.wait_group %0;" :: "n"(N) : "memory");
}
__device__ __forceinline__ void split2_f16(float v0, float v1,
                                           uint32_t& hi2, uint32_t& lo2) {
    __half2 h = __floats2half2_rn(v0, v1);          // low = v0
    float2  f = __half22float2(h);
    __half2 l = __floats2half2_rn(v0 - f.x, v1 - f.y);
    hi2 = *(uint32_t*)&h;
    lo2 = *(uint32_t*)&l;
}
#define MMA(c0, c1, c2, c3, a0, a1, a2, a3, b0, b1)                        \
    asm volatile(                                                          \
        "mma.sync.aligned.m16n8k16.row.col.f32.f16.f16.f32 "               \
        "{%0,%1,%2,%3}, {%4,%5,%6,%7}, {%8,%9}, {%0,%1,%2,%3};"            \
        : "+f"(c0), "+f"(c1), "+f"(c2), "+f"(c3)                           \
        : "r"(a0), "r"(a1), "r"(a2), "r"(a3), "r"(b0), "r"(b1))

// ============================================================================
// Setup: group examples by op; perm[] + per-128-row tile descriptors
// ============================================================================
__global__ void setup_kernel(const int* __restrict__ op_idx)
{
    __shared__ int cnt[O_DIM];
    __shared__ int cur[O_DIM];
    const int tid = threadIdx.x;
    const int nt  = blockDim.x;

    if (tid < O_DIM) cnt[tid] = 0;
    __syncthreads();
    for (int b = tid; b < B_DIM; b += nt)
        atomicAdd(&cnt[op_idx[b]], 1);
    __syncthreads();

    if (tid == 0) {
        int acc = 0, ntile = 0;
        for (int o = 0; o < O_DIM; o++) {
            cur[o] = acc;
            const int c = cnt[o];
            for (int t = 0; t < c; t += TM) {
                g_tile_op[ntile]    = o;
                g_tile_start[ntile] = acc + t;
                g_tile_rows[ntile]  = (c - t < TM) ? (c - t) : TM;
                ntile++;
            }
            acc += c;
        }
        g_num_tiles = ntile;
    }
    __syncthreads();

    for (int b = tid; b < B_DIM; b += nt) {
        const int o = op_idx[b];
        const int p = atomicAdd(&cur[o], 1);
        g_perm[p] = b;
    }
}

// ============================================================================
// Pre-pass: W[k][o][n] fp32 -> Wh/Wl[o][kp][n] packed half2 k-pairs
// ============================================================================
__global__ void convert_w_kernel(const float* __restrict__ W,
                                 uint32_t* __restrict__ Wh,
                                 uint32_t* __restrict__ Wl)
{
    const size_t i = (size_t)blockIdx.x * NTHREADS + threadIdx.x;  // < 16*512*1024
    const int n  = (int)(i & 1023);
    const int kp = (int)((i >> 10) & 511);
    const int o  = (int)(i >> 19);
    const float v0 = W[(size_t)(2 * kp)     * KOH + o * H_DIM + n];
    const float v1 = W[(size_t)(2 * kp + 1) * KOH + o * H_DIM + n];
    uint32_t hi, lo;
    split2_f16(v0, v1, hi, lo);
    Wh[i] = hi;
    Wl[i] = lo;
}

// Pre-pass: x[b][e] fp32 -> xh/xl[b][kp] packed half2 k-pairs
__global__ void convert_x_kernel(const float* __restrict__ x,
                                 uint32_t* __restrict__ xh,
                                 uint32_t* __restrict__ xl)
{
    const size_t i = (size_t)blockIdx.x * NTHREADS + threadIdx.x;  // < 4096*512
    const float2 v = *(const float2*)(x + 2 * i);   // i = b*512+kp -> 2i = b*1024+2kp
    uint32_t hi, lo;
    split2_f16(v.x, v.y, hi, lo);
    xh[i] = hi;
    xl[i] = lo;
}

// ============================================================================
// Grouped GEMM, mma.sync m16n8k16 fp16, 3-pass (hh + hl + lh).
// All operands pre-split/packed in gmem; tiles stream in via cp.async
// (no register round trip, no cvt in the mainloop). 3-stage ring, one
// __syncthreads per chunk.
//   LAYER 1: A = xh/xl rows gathered via perm; out -> g_h1h/g_h1l (permuted)
//   LAYER 2: A = g_h1h/g_h1l contiguous;       out -> fp32, scatter via perm
// ============================================================================
template <int LAYER>
__global__ __launch_bounds__(NTHREADS, 2)
void gemm_mma(const uint32_t* __restrict__ Ahg, const uint32_t* __restrict__ Alg,
              const uint32_t* __restrict__ Whg, const uint32_t* __restrict__ Wlg,
              const float* __restrict__ bias, float* __restrict__ Out)
{
    const int tile = blockIdx.x;
    if (tile >= g_num_tiles) return;

    const int op        = g_tile_op[tile];
    const int row_start = g_tile_start[tile];
    const int nrows     = g_tile_rows[tile];
    const int col_base  = blockIdx.y * TN;
    const int tid       = threadIdx.x;
    const int lid       = tid & 31;
    const int wid       = tid >> 5;
    const int warp_m    = wid >> 2;    // 0..1  (64 rows)
    const int warp_n    = wid & 3;     // 0..3  (32 cols)
    const int g         = lid >> 2;    // 0..7
    const int tig       = lid & 3;     // 0..3

    extern __shared__ uint32_t smem[];
    const uint32_t sb = smem_u32(smem);

    // A cp.async mapping: thread -> (row = tid>>1, half = tid&1); 4x16B per chunk
    const int arow  = tid >> 1;
    const int ahalf = tid & 1;
    const int arr   = (arow < nrows) ? arow : 0;
    const int asrc  = (LAYER == 1) ? g_perm[row_start + arr] : (row_start + arr);
    const uint32_t* Aps = (ahalf ? Alg : Ahg) + (size_t)asrc * KPE;
    const uint32_t a_dst = (ahalf ? ST_AL * 4 : 0) + arow * (APITCH * 4);

    // B cp.async mapping: thread -> (kp = tid>>4, seg-pair = tid&15); 2x16B hi + 2x16B lo
    const int bkp = tid >> 4;
    const int bsg = tid & 15;
    const uint32_t* Bhs = Whg + ((size_t)op * KPE + bkp) * H_DIM + col_base + bsg * 8;
    const uint32_t* Bls = Wlg + ((size_t)op * KPE + bkp) * H_DIM + col_base + bsg * 8;
    const uint32_t bh_dst = ST_BH * 4 + bkp * (BPITCH * 4) + bsg * 32;
    const uint32_t bl_dst = ST_BL * 4 + bkp * (BPITCH * 4) + bsg * 32;

    auto issue = [&](int kc) {
        const uint32_t st = sb + (uint32_t)(kc % NSTAGE) * STAGE_BYTES;
        const uint32_t* as = Aps + kc * KPC;
        #pragma unroll
        for (int j = 0; j < 4; j++)
            cp_async16(st + a_dst + j * 16, as + j * 4);
        const uint32_t* bh = Bhs + (size_t)kc * KPC * H_DIM;
        const uint32_t* bl = Bls + (size_t)kc * KPC * H_DIM;
        cp_async16(st + bh_dst,      bh);
        cp_async16(st + bh_dst + 16, bh + 4);
        cp_async16(st + bl_dst,      bl);
        cp_async16(st + bl_dst + 16, bl + 4);
    };

    float acc[4][4][4];
    #pragma unroll
    for (int mt = 0; mt < 4; mt++)
        #pragma unroll
        for (int nt = 0; nt < 4; nt++)
            #pragma unroll
            for (int e = 0; e < 4; e++) acc[mt][nt][e] = 0.f;

    // ---- prologue: stages 0,1 in flight ----
    issue(0); cp_commit();
    issue(1); cp_commit();

    for (int kc = 0; kc < NCHUNK; kc++) {
        cp_wait<1>();      // group carrying chunk kc complete (1 newer may pend)
        __syncthreads();   // publish smem; all threads past compute of kc-1

        if (kc + 2 < NCHUNK) issue(kc + 2);
        cp_commit();       // commit every iter (possibly empty) keeps counts exact

        const uint32_t* st = smem + (kc % NSTAGE) * STAGE_U32;
        const uint32_t* Ah = st + ST_AH;
        const uint32_t* Al = st + ST_AL;
        const uint32_t* Bh = st + ST_BH;
        const uint32_t* Bl = st + ST_BL;

        #pragma unroll
        for (int ks = 0; ks < 2; ks++) {
            const int k0 = ks * 8 + tig;
            const int k1 = k0 + 4;

            uint32_t bh[4][2], bl[4][2];
            #pragma unroll
            for (int nt = 0; nt < 4; nt++) {
                const int c = warp_n * 32 + nt * 8 + g;
                bh[nt][0] = Bh[k0 * BPITCH + c];
                bh[nt][1] = Bh[k1 * BPITCH + c];
                bl[nt][0] = Bl[k0 * BPITCH + c];
                bl[nt][1] = Bl[k1 * BPITCH + c];
            }
            #pragma unroll
            for (int mt = 0; mt < 4; mt++) {
                const int m0 = warp_m * 64 + mt * 16 + g;
                uint32_t ah0 = Ah[m0 * APITCH + k0];
                uint32_t ah1 = Ah[(m0 + 8) * APITCH + k0];
                uint32_t ah2 = Ah[m0 * APITCH + k1];
                uint32_t ah3 = Ah[(m0 + 8) * APITCH + k1];
                uint32_t al0 = Al[m0 * APITCH + k0];
                uint32_t al1 = Al[(m0 + 8) * APITCH + k0];
                uint32_t al2 = Al[m0 * APITCH + k1];
                uint32_t al3 = Al[(m0 + 8) * APITCH + k1];
                #pragma unroll
                for (int nt = 0; nt < 4; nt++)
                    MMA(acc[mt][nt][0], acc[mt][nt][1], acc[mt][nt][2], acc[mt][nt][3],
                        ah0, ah1, ah2, ah3, bh[nt][0], bh[nt][1]);
                #pragma unroll
                for (int nt = 0; nt < 4; nt++)
                    MMA(acc[mt][nt][0], acc[mt][nt][1], acc[mt][nt][2], acc[mt][nt][3],
                        ah0, ah1, ah2, ah3, bl[nt][0], bl[nt][1]);
                #pragma unroll
                for (int nt = 0; nt < 4; nt++)
                    MMA(acc[mt][nt][0], acc[mt][nt][1], acc[mt][nt][2], acc[mt][nt][3],
                        al0, al1, al2, al3, bh[nt][0], bh[nt][1]);
            }
        }
    }

    // ---- epilogue ----
    float2 bb[4];
    #pragma unroll
    for (int nt = 0; nt < 4; nt++) {
        const int c = col_base + warp_n * 32 + nt * 8 + 2 * tig;
        bb[nt] = *(const float2*)(bias + (size_t)op * H_DIM + c);
    }
    #pragma unroll
    for (int mt = 0; mt < 4; mt++) {
        #pragma unroll
        for (int h = 0; h < 2; h++) {
            const int r = warp_m * 64 + mt * 16 + h * 8 + g;
            if (r < nrows) {
                if (LAYER == 1) {
                    // bias+relu then split/pack -> h1 stays in permuted order
                    const size_t rowbase = (size_t)(row_start + r) * KPE;
                    #pragma unroll
                    for (int nt = 0; nt < 4; nt++) {
                        const int kpc = col_base / 2 + warp_n * 16 + nt * 4 + tig;
                        float vx = fmaxf(acc[mt][nt][2 * h + 0] + bb[nt].x, 0.f);
                        float vy = fmaxf(acc[mt][nt][2 * h + 1] + bb[nt].y, 0.f);
                        uint32_t hi, lo;
                        split2_f16(vx, vy, hi, lo);
                        g_h1h[rowbase + kpc] = hi;
                        g_h1l[rowbase + kpc] = lo;
                    }
                } else {
                    const int dst = g_perm[row_start + r];
                    float* orow = Out + (size_t)dst * H_DIM + col_base
                                      + warp_n * 32 + 2 * tig;
                    #pragma unroll
                    for (int nt = 0; nt < 4; nt++) {
                        float2 v;
                        v.x = fmaxf(acc[mt][nt][2 * h + 0] + bb[nt].x, 0.f);
                        v.y = fmaxf(acc[mt][nt][2 * h + 1] + bb[nt].y, 0.f);
                        *(float2*)(orow + nt * 8) = v;
                    }
                }
            }
        }
    }
}

// ============================================================================
// Launch
// ============================================================================
extern "C" void kernel_launch(void* const* d_in, const int* in_sizes, int n_in,
                              void* d_out, int out_size)
{
    const float* x      = (const float*)d_in[0];
    const int*   op_idx = (const int*)  d_in[1];
    const float* W1     = (const float*)d_in[2];
    const float* b1     = (const float*)d_in[3];
    const float* W2     = (const float*)d_in[4];
    const float* b2     = (const float*)d_in[5];
    float*       out    = (float*)d_out;
    (void)in_sizes; (void)n_in; (void)out_size;

    uint32_t *w1h, *w1l, *w2h, *w2l, *xh, *xl, *h1h, *h1l;
    cudaGetSymbolAddress((void**)&w1h, g_w1h);
    cudaGetSymbolAddress((void**)&w1l, g_w1l);
    cudaGetSymbolAddress((void**)&w2h, g_w2h);
    cudaGetSymbolAddress((void**)&w2l, g_w2l);
    cudaGetSymbolAddress((void**)&xh,  g_xh);
    cudaGetSymbolAddress((void**)&xl,  g_xl);
    cudaGetSymbolAddress((void**)&h1h, g_h1h);
    cudaGetSymbolAddress((void**)&h1l, g_h1l);

    cudaFuncSetAttribute(gemm_mma<1>, cudaFuncAttributeMaxDynamicSharedMemorySize, SMEM_NEED);
    cudaFuncSetAttribute(gemm_mma<2>, cudaFuncAttributeMaxDynamicSharedMemorySize, SMEM_NEED);

    setup_kernel<<<1, 512>>>(op_idx);
    convert_x_kernel<<<(B_DIM * KPE) / NTHREADS, NTHREADS>>>(x, xh, xl);
    convert_w_kernel<<<(O_DIM * KPE * H_DIM) / NTHREADS, NTHREADS>>>(W1, w1h, w1l);
    convert_w_kernel<<<(O_DIM * KPE * H_DIM) / NTHREADS, NTHREADS>>>(W2, w2h, w2l);

    dim3 grid(MAX_TILES, H_DIM / TN);
    gemm_mma<1><<<grid, NTHREADS, SMEM_NEED>>>(xh,  xl,  w1h, w1l, b1, nullptr);
    gemm_mma<2><<<grid, NTHREADS, SMEM_NEED>>>(h1h, h1l, w2h, w2l, b2, out);
}

// round 13
// speedup vs baseline: 1.2078x; 1.2078x over previous
#include <cuda_runtime.h>
#include <cuda_fp16.h>
#include <cstdint>

// Problem constants
#define B_DIM 4096
#define E_DIM 1024
#define O_DIM 16
#define H_DIM 1024
#define KOH   (O_DIM * H_DIM)
#define KPE   512                        // k-pairs per full K (1024/2)

// Tiling
#define TM 128
#define TN 128
#define KPC 16                           // k-pairs per chunk (32 floats)
#define NCHUNK (KPE / KPC)               // 32
#define NTHREADS 256
#define MAX_TILES (B_DIM / TM + O_DIM)   // 48

// smem (u32 units). A(hi only): [m][kp] pitch 20 (banks 20g+tig all-distinct);
// B: [kp][n] pitch 136 (banks 8tig+8nt+g all-distinct). All cp.async-filled.
#define APITCH 20
#define BPITCH 136
#define A_TILE (TM * APITCH)             // 2560
#define B_TILE (KPC * BPITCH)            // 2176
#define ST_AH 0
#define ST_BH A_TILE                     // 2560
#define ST_BL (A_TILE + B_TILE)          // 4736
#define STAGE_U32 (A_TILE + 2 * B_TILE)  // 6912
#define STAGE_BYTES (STAGE_U32 * 4)      // 27648
#define NSTAGE 4
#define SMEM_NEED (NSTAGE * STAGE_BYTES) // 110592 (x2 CTAs = 221KB/SM)

// ---- device scratch (allocation-free __device__ globals) ----
__device__ int      g_perm[B_DIM];
__device__ int      g_tile_op[MAX_TILES];
__device__ int      g_tile_start[MAX_TILES];
__device__ int      g_tile_rows[MAX_TILES];
__device__ int      g_num_tiles;
__device__ uint32_t g_w1h[(size_t)O_DIM * KPE * H_DIM];   // [o][kp][n] packed half2
__device__ uint32_t g_w1l[(size_t)O_DIM * KPE * H_DIM];
__device__ uint32_t g_w2h[(size_t)O_DIM * KPE * H_DIM];
__device__ uint32_t g_w2l[(size_t)O_DIM * KPE * H_DIM];
__device__ uint32_t g_xh[(size_t)B_DIM * KPE];            // [b][kp] hi only
__device__ uint32_t g_h1h[(size_t)B_DIM * KPE];           // [permuted row][kp]

// ============================================================================
// Helpers — baseline PTX only (cp.async + mma.sync m16n8k16, both sm_80+)
// ============================================================================
__device__ __forceinline__ uint32_t smem_u32(const void* p) {
    uint32_t a;
    asm("{ .reg .u64 t; cvta.to.shared.u64 t, %1; cvt.u32.u64 %0, t; }"
        : "=r"(a) : "l"(p));
    return a;
}
__device__ __forceinline__ void cp_async16(uint32_t dst, const void* src) {
    asm volatile("cp.async.ca.shared.global [%0], [%1], 16;" :: "r"(dst), "l"(src));
}
__device__ __forceinline__ void cp_commit() {
    asm volatile("cp.async.commit_group;" ::: "memory");
}
template <int N>
__device__ __forceinline__ void cp_wait() {
    asm volatile("cp.async.wait_group %0;" :: "n"(N) : "memory");
}
// Pack pair to f16 (hi) and f16 residual (lo)
__device__ __forceinline__ void split2_f16(float v0, float v1,
                                           uint32_t& hi2, uint32_t& lo2) {
    __half2 h = __floats2half2_rn(v0, v1);          // low = v0
    float2  f = __half22float2(h);
    __half2 l = __floats2half2_rn(v0 - f.x, v1 - f.y);
    hi2 = *(uint32_t*)&h;
    lo2 = *(uint32_t*)&l;
}
__device__ __forceinline__ uint32_t pack2_f16(float v0, float v1) {
    __half2 h = __floats2half2_rn(v0, v1);
    return *(uint32_t*)&h;
}
#define MMA(c0, c1, c2, c3, a0, a1, a2, a3, b0, b1)                        \
    asm volatile(                                                          \
        "mma.sync.aligned.m16n8k16.row.col.f32.f16.f16.f32 "               \
        "{%0,%1,%2,%3}, {%4,%5,%6,%7}, {%8,%9}, {%0,%1,%2,%3};"            \
        : "+f"(c0), "+f"(c1), "+f"(c2), "+f"(c3)                           \
        : "r"(a0), "r"(a1), "r"(a2), "r"(a3), "r"(b0), "r"(b1))

// ============================================================================
// Setup: group examples by op; perm[] + per-128-row tile descriptors
// ============================================================================
__global__ void setup_kernel(const int* __restrict__ op_idx)
{
    __shared__ int cnt[O_DIM];
    __shared__ int cur[O_DIM];
    const int tid = threadIdx.x;
    const int nt  = blockDim.x;

    if (tid < O_DIM) cnt[tid] = 0;
    __syncthreads();
    for (int b = tid; b < B_DIM; b += nt)
        atomicAdd(&cnt[op_idx[b]], 1);
    __syncthreads();

    if (tid == 0) {
        int acc = 0, ntile = 0;
        for (int o = 0; o < O_DIM; o++) {
            cur[o] = acc;
            const int c = cnt[o];
            for (int t = 0; t < c; t += TM) {
                g_tile_op[ntile]    = o;
                g_tile_start[ntile] = acc + t;
                g_tile_rows[ntile]  = (c - t < TM) ? (c - t) : TM;
                ntile++;
            }
            acc += c;
        }
        g_num_tiles = ntile;
    }
    __syncthreads();

    for (int b = tid; b < B_DIM; b += nt) {
        const int o = op_idx[b];
        const int p = atomicAdd(&cur[o], 1);
        g_perm[p] = b;
    }
}

// ============================================================================
// Pre-pass: W[k][o][n] fp32 -> Wh/Wl[o][kp][n] packed half2 k-pairs.
// float4 reads (2 rows), uint4 writes — fully coalesced both sides.
// ============================================================================
__global__ void convert_w_kernel(const float* __restrict__ W,
                                 uint32_t* __restrict__ Wh,
                                 uint32_t* __restrict__ Wl)
{
    const size_t i = (size_t)blockIdx.x * NTHREADS + threadIdx.x;  // < 16*512*256
    const int n4 = (int)(i & 255);          // group of 4 n
    const int kp = (int)((i >> 8) & 511);
    const int o  = (int)(i >> 17);
    const float4 r0 = *(const float4*)(W + (size_t)(2 * kp)     * KOH + o * H_DIM + n4 * 4);
    const float4 r1 = *(const float4*)(W + (size_t)(2 * kp + 1) * KOH + o * H_DIM + n4 * 4);
    uint4 h4, l4;
    split2_f16(r0.x, r1.x, h4.x, l4.x);
    split2_f16(r0.y, r1.y, h4.y, l4.y);
    split2_f16(r0.z, r1.z, h4.z, l4.z);
    split2_f16(r0.w, r1.w, h4.w, l4.w);
    const size_t oidx = ((size_t)o * KPE + kp) * H_DIM + n4 * 4;
    *(uint4*)(Wh + oidx) = h4;
    *(uint4*)(Wl + oidx) = l4;
}

// Pre-pass: x[b][e] fp32 -> xh[b][kp] packed half2 (hi only)
__global__ void convert_x_kernel(const float* __restrict__ x,
                                 uint32_t* __restrict__ xh)
{
    const size_t i = (size_t)blockIdx.x * NTHREADS + threadIdx.x;  // < B*KPE/4
    const float4 v0 = *(const float4*)(x + i * 8);
    const float4 v1 = *(const float4*)(x + i * 8 + 4);
    uint4 h4;
    h4.x = pack2_f16(v0.x, v0.y);
    h4.y = pack2_f16(v0.z, v0.w);
    h4.z = pack2_f16(v1.x, v1.y);
    h4.w = pack2_f16(v1.z, v1.w);
    *(uint4*)(xh + i * 4) = h4;
}

// ============================================================================
// Grouped GEMM, mma.sync m16n8k16 fp16, 2-pass (hh + hl):
//   out = xh*(Wh + Wl)  — only the activation side is fp16-quantized.
// All operands pre-packed in gmem; tiles stream via cp.async; 4-stage ring,
// one __syncthreads per chunk. 64 HMMA per warp per chunk.
//   LAYER 1: A = xh rows gathered via perm; out -> g_h1h (permuted, packed)
//   LAYER 2: A = g_h1h contiguous;          out -> fp32, scatter via perm
// ============================================================================
template <int LAYER>
__global__ __launch_bounds__(NTHREADS, 2)
void gemm_mma(const uint32_t* __restrict__ Ahg,
              const uint32_t* __restrict__ Whg, const uint32_t* __restrict__ Wlg,
              const float* __restrict__ bias, float* __restrict__ Out)
{
    const int tile = blockIdx.x;
    if (tile >= g_num_tiles) return;

    const int op        = g_tile_op[tile];
    const int row_start = g_tile_start[tile];
    const int nrows     = g_tile_rows[tile];
    const int col_base  = blockIdx.y * TN;
    const int tid       = threadIdx.x;
    const int lid       = tid & 31;
    const int wid       = tid >> 5;
    const int warp_m    = wid >> 2;    // 0..1  (64 rows)
    const int warp_n    = wid & 3;     // 0..3  (32 cols)
    const int g         = lid >> 2;    // 0..7
    const int tig       = lid & 3;     // 0..3

    extern __shared__ uint32_t smem[];
    const uint32_t sb = smem_u32(smem);

    // A cp.async: thread -> (row = tid>>1, q = tid&1); 2x16B per chunk
    const int arow = tid >> 1;
    const int aq   = tid & 1;
    const int arr  = (arow < nrows) ? arow : 0;
    const int asrc = (LAYER == 1) ? g_perm[row_start + arr] : (row_start + arr);
    const uint32_t* Aps = Ahg + (size_t)asrc * KPE + aq * 8;
    const uint32_t a_dst = (uint32_t)(arow * APITCH + aq * 8) * 4u;

    // B cp.async: thread -> (kp = tid>>4, sg = tid&15); 2x16B hi + 2x16B lo
    const int bkp = tid >> 4;
    const int bsg = tid & 15;
    const uint32_t* Bhs = Whg + ((size_t)op * KPE + bkp) * H_DIM + col_base + bsg * 8;
    const uint32_t* Bls = Wlg + ((size_t)op * KPE + bkp) * H_DIM + col_base + bsg * 8;
    const uint32_t bh_dst = (uint32_t)(ST_BH + bkp * BPITCH + bsg * 8) * 4u;
    const uint32_t bl_dst = (uint32_t)(ST_BL + bkp * BPITCH + bsg * 8) * 4u;

    auto issue = [&](int kc) {
        const uint32_t st = sb + (uint32_t)(kc % NSTAGE) * STAGE_BYTES;
        const uint32_t* as = Aps + kc * KPC;
        cp_async16(st + a_dst,      as);
        cp_async16(st + a_dst + 16, as + 4);
        const uint32_t* bh = Bhs + (size_t)kc * KPC * H_DIM;
        const uint32_t* bl = Bls + (size_t)kc * KPC * H_DIM;
        cp_async16(st + bh_dst,      bh);
        cp_async16(st + bh_dst + 16, bh + 4);
        cp_async16(st + bl_dst,      bl);
        cp_async16(st + bl_dst + 16, bl + 4);
    };

    float acc[4][4][4];
    #pragma unroll
    for (int mt = 0; mt < 4; mt++)
        #pragma unroll
        for (int nt = 0; nt < 4; nt++)
            #pragma unroll
            for (int e = 0; e < 4; e++) acc[mt][nt][e] = 0.f;

    // ---- prologue: stages 0..2 in flight ----
    issue(0); cp_commit();
    issue(1); cp_commit();
    issue(2); cp_commit();

    for (int kc = 0; kc < NCHUNK; kc++) {
        cp_wait<2>();      // groups through chunk kc complete (2 newer may pend)
        __syncthreads();   // publish smem; all threads past compute of kc-1

        if (kc + 3 < NCHUNK) issue(kc + 3);
        cp_commit();       // commit every iter keeps group counts exact

        const uint32_t* st = smem + (kc % NSTAGE) * STAGE_U32;
        const uint32_t* Ah = st + ST_AH;
        const uint32_t* Bh = st + ST_BH;
        const uint32_t* Bl = st + ST_BL;

        #pragma unroll
        for (int ks = 0; ks < 2; ks++) {
            const int k0 = ks * 8 + tig;
            const int k1 = k0 + 4;

            uint32_t bh[4][2], bl[4][2];
            #pragma unroll
            for (int nt = 0; nt < 4; nt++) {
                const int c = warp_n * 32 + nt * 8 + g;
                bh[nt][0] = Bh[k0 * BPITCH + c];
                bh[nt][1] = Bh[k1 * BPITCH + c];
                bl[nt][0] = Bl[k0 * BPITCH + c];
                bl[nt][1] = Bl[k1 * BPITCH + c];
            }
            #pragma unroll
            for (int mt = 0; mt < 4; mt++) {
                const int m0 = warp_m * 64 + mt * 16 + g;
                uint32_t a0 = Ah[m0 * APITCH + k0];
                uint32_t a1 = Ah[(m0 + 8) * APITCH + k0];
                uint32_t a2 = Ah[m0 * APITCH + k1];
                uint32_t a3 = Ah[(m0 + 8) * APITCH + k1];
                #pragma unroll
                for (int nt = 0; nt < 4; nt++)
                    MMA(acc[mt][nt][0], acc[mt][nt][1], acc[mt][nt][2], acc[mt][nt][3],
                        a0, a1, a2, a3, bh[nt][0], bh[nt][1]);
                #pragma unroll
                for (int nt = 0; nt < 4; nt++)
                    MMA(acc[mt][nt][0], acc[mt][nt][1], acc[mt][nt][2], acc[mt][nt][3],
                        a0, a1, a2, a3, bl[nt][0], bl[nt][1]);
            }
        }
    }

    // ---- epilogue ----
    float2 bb[4];
    #pragma unroll
    for (int nt = 0; nt < 4; nt++) {
        const int c = col_base + warp_n * 32 + nt * 8 + 2 * tig;
        bb[nt] = *(const float2*)(bias + (size_t)op * H_DIM + c);
    }
    #pragma unroll
    for (int mt = 0; mt < 4; mt++) {
        #pragma unroll
        for (int h = 0; h < 2; h++) {
            const int r = warp_m * 64 + mt * 16 + h * 8 + g;
            if (r < nrows) {
                if (LAYER == 1) {
                    // bias+relu, pack to f16 pairs (hi only) in permuted order
                    const size_t rowbase = (size_t)(row_start + r) * KPE;
                    #pragma unroll
                    for (int nt = 0; nt < 4; nt++) {
                        const int kpc = col_base / 2 + warp_n * 16 + nt * 4 + tig;
                        float vx = fmaxf(acc[mt][nt][2 * h + 0] + bb[nt].x, 0.f);
                        float vy = fmaxf(acc[mt][nt][2 * h + 1] + bb[nt].y, 0.f);
                        g_h1h[rowbase + kpc] = pack2_f16(vx, vy);
                    }
                } else {
                    const int dst = g_perm[row_start + r];
                    float* orow = Out + (size_t)dst * H_DIM + col_base
                                      + warp_n * 32 + 2 * tig;
                    #pragma unroll
                    for (int nt = 0; nt < 4; nt++) {
                        float2 v;
                        v.x = fmaxf(acc[mt][nt][2 * h + 0] + bb[nt].x, 0.f);
                        v.y = fmaxf(acc[mt][nt][2 * h + 1] + bb[nt].y, 0.f);
                        *(float2*)(orow + nt * 8) = v;
                    }
                }
            }
        }
    }
}

// ============================================================================
// Launch
// ============================================================================
extern "C" void kernel_launch(void* const* d_in, const int* in_sizes, int n_in,
                              void* d_out, int out_size)
{
    const float* x      = (const float*)d_in[0];
    const int*   op_idx = (const int*)  d_in[1];
    const float* W1     = (const float*)d_in[2];
    const float* b1     = (const float*)d_in[3];
    const float* W2     = (const float*)d_in[4];
    const float* b2     = (const float*)d_in[5];
    float*       out    = (float*)d_out;
    (void)in_sizes; (void)n_in; (void)out_size;

    uint32_t *w1h, *w1l, *w2h, *w2l, *xh, *h1h;
    cudaGetSymbolAddress((void**)&w1h, g_w1h);
    cudaGetSymbolAddress((void**)&w1l, g_w1l);
    cudaGetSymbolAddress((void**)&w2h, g_w2h);
    cudaGetSymbolAddress((void**)&w2l, g_w2l);
    cudaGetSymbolAddress((void**)&xh,  g_xh);
    cudaGetSymbolAddress((void**)&h1h, g_h1h);

    cudaFuncSetAttribute(gemm_mma<1>, cudaFuncAttributeMaxDynamicSharedMemorySize, SMEM_NEED);
    cudaFuncSetAttribute(gemm_mma<2>, cudaFuncAttributeMaxDynamicSharedMemorySize, SMEM_NEED);

    setup_kernel<<<1, 512>>>(op_idx);
    convert_x_kernel<<<(B_DIM * KPE / 4) / NTHREADS, NTHREADS>>>(x, xh);
    convert_w_kernel<<<(O_DIM * KPE * 256) / NTHREADS, NTHREADS>>>(W1, w1h, w1l);
    convert_w_kernel<<<(O_DIM * KPE * 256) / NTHREADS, NTHREADS>>>(W2, w2h, w2l);

    dim3 grid(MAX_TILES, H_DIM / TN);
    gemm_mma<1><<<grid, NTHREADS, SMEM_NEED>>>(xh,  w1h, w1l, b1, nullptr);
    gemm_mma<2><<<grid, NTHREADS, SMEM_NEED>>>(h1h, w2h, w2l, b2, out);
}

// round 17
// speedup vs baseline: 2.4270x; 2.0094x over previous
#include <cuda_runtime.h>
#include <cuda_fp16.h>
#include <cstdint>

// Problem constants
#define B_DIM 4096
#define E_DIM 1024
#define O_DIM 16
#define H_DIM 1024
#define KOH   (O_DIM * H_DIM)
#define KPE   512                        // k-pairs per full K (1024/2)

// Tiling: 128 x 64 CTA tile, 8 warps as 4(m) x 2(n), warp tile 32x32
#define TM 128
#define TN 64
#define KPC 16                           // k-pairs per chunk (32 floats)
#define NCHUNK (KPE / KPC)               // 32
#define NTHREADS 256
#define MAX_TILES (B_DIM / TM + O_DIM)   // 48

// smem (u32 units). A: [m][kp] pitch 20 (banks 20g+tig distinct);
// B: [kp][n] pitch 72 (72 mod 32 = 8 -> banks 8tig+g distinct).
#define APITCH 20
#define BPITCH 72
#define A_TILE (TM * APITCH)             // 2560
#define B_TILE (KPC * BPITCH)            // 1152
#define ST_AH 0
#define ST_BH A_TILE                     // 2560
#define STAGE_U32 (A_TILE + B_TILE)      // 3712
#define STAGE_BYTES (STAGE_U32 * 4)      // 14848
#define NSTAGE 4
#define SMEM_NEED (NSTAGE * STAGE_BYTES) // 59392 (x3 CTAs = 178KB/SM)

// ---- device scratch (allocation-free __device__ globals) ----
__device__ int      g_perm[B_DIM];
__device__ int      g_tile_op[MAX_TILES];
__device__ int      g_tile_start[MAX_TILES];
__device__ int      g_tile_rows[MAX_TILES];
__device__ int      g_num_tiles;
__device__ uint32_t g_w1h[(size_t)O_DIM * KPE * H_DIM];   // [o][kp][n] packed half2
__device__ uint32_t g_w2h[(size_t)O_DIM * KPE * H_DIM];
__device__ uint32_t g_xh[(size_t)B_DIM * KPE];            // [b][kp]
__device__ uint32_t g_h1h[(size_t)B_DIM * KPE];           // [permuted row][kp]

// ============================================================================
// Helpers — baseline PTX only (cp.async + mma.sync m16n8k16, both sm_80+)
// ============================================================================
__device__ __forceinline__ uint32_t smem_u32(const void* p) {
    uint32_t a;
    asm("{ .reg .u64 t; cvta.to.shared.u64 t, %1; cvt.u32.u64 %0, t; }"
        : "=r"(a) : "l"(p));
    return a;
}
__device__ __forceinline__ void cp_async16(uint32_t dst, const void* src) {
    asm volatile("cp.async.ca.shared.global [%0], [%1], 16;" :: "r"(dst), "l"(src));
}
__device__ __forceinline__ void cp_commit() {
    asm volatile("cp.async.commit_group;" ::: "memory");
}
template <int N>
__device__ __forceinline__ void cp_wait() {
    asm volatile("cp.async.wait_group %0;" :: "n"(N) : "memory");
}
__device__ __forceinline__ uint32_t pack2_f16(float v0, float v1) {
    __half2 h = __floats2half2_rn(v0, v1);
    return *(uint32_t*)&h;
}
#define MMA(c0, c1, c2, c3, a0, a1, a2, a3, b0, b1)                        \
    asm volatile(                                                          \
        "mma.sync.aligned.m16n8k16.row.col.f32.f16.f16.f32 "               \
        "{%0,%1,%2,%3}, {%4,%5,%6,%7}, {%8,%9}, {%0,%1,%2,%3};"            \
        : "+f"(c0), "+f"(c1), "+f"(c2), "+f"(c3)                           \
        : "r"(a0), "r"(a1), "r"(a2), "r"(a3), "r"(b0), "r"(b1))

// ============================================================================
// Setup: group examples by op; perm[] + per-128-row tile descriptors
// ============================================================================
__global__ void setup_kernel(const int* __restrict__ op_idx)
{
    __shared__ int cnt[O_DIM];
    __shared__ int cur[O_DIM];
    const int tid = threadIdx.x;
    const int nt  = blockDim.x;

    if (tid < O_DIM) cnt[tid] = 0;
    __syncthreads();
    for (int b = tid; b < B_DIM; b += nt)
        atomicAdd(&cnt[op_idx[b]], 1);
    __syncthreads();

    if (tid == 0) {
        int acc = 0, ntile = 0;
        for (int o = 0; o < O_DIM; o++) {
            cur[o] = acc;
            const int c = cnt[o];
            for (int t = 0; t < c; t += TM) {
                g_tile_op[ntile]    = o;
                g_tile_start[ntile] = acc + t;
                g_tile_rows[ntile]  = (c - t < TM) ? (c - t) : TM;
                ntile++;
            }
            acc += c;
        }
        g_num_tiles = ntile;
    }
    __syncthreads();

    for (int b = tid; b < B_DIM; b += nt) {
        const int o = op_idx[b];
        const int p = atomicAdd(&cur[o], 1);
        g_perm[p] = b;
    }
}

// ============================================================================
// Pre-pass: W[k][o][n] fp32 -> Wh[o][kp][n] packed half2 k-pairs (hi only).
// ============================================================================
__global__ void convert_w_kernel(const float* __restrict__ W,
                                 uint32_t* __restrict__ Wh)
{
    const size_t i = (size_t)blockIdx.x * NTHREADS + threadIdx.x;  // < 16*512*256
    const int n4 = (int)(i & 255);
    const int kp = (int)((i >> 8) & 511);
    const int o  = (int)(i >> 17);
    const float4 r0 = *(const float4*)(W + (size_t)(2 * kp)     * KOH + o * H_DIM + n4 * 4);
    const float4 r1 = *(const float4*)(W + (size_t)(2 * kp + 1) * KOH + o * H_DIM + n4 * 4);
    uint4 h4;
    h4.x = pack2_f16(r0.x, r1.x);
    h4.y = pack2_f16(r0.y, r1.y);
    h4.z = pack2_f16(r0.z, r1.z);
    h4.w = pack2_f16(r0.w, r1.w);
    *(uint4*)(Wh + ((size_t)o * KPE + kp) * H_DIM + n4 * 4) = h4;
}

// Pre-pass: x[b][e] fp32 -> xh[b][kp] packed half2
__global__ void convert_x_kernel(const float* __restrict__ x,
                                 uint32_t* __restrict__ xh)
{
    const size_t i = (size_t)blockIdx.x * NTHREADS + threadIdx.x;  // < B*KPE/4
    const float4 v0 = *(const float4*)(x + i * 8);
    const float4 v1 = *(const float4*)(x + i * 8 + 4);
    uint4 h4;
    h4.x = pack2_f16(v0.x, v0.y);
    h4.y = pack2_f16(v0.z, v0.w);
    h4.z = pack2_f16(v1.x, v1.y);
    h4.w = pack2_f16(v1.z, v1.w);
    *(uint4*)(xh + i * 4) = h4;
}

// ============================================================================
// Grouped GEMM, mma.sync m16n8k16 fp16, single pass (both sides quantized).
// 128x64 tiles -> ~528 CTAs/layer, occ 3: throughput- not latency-bound.
// cp.async 4-stage ring, one __syncthreads per chunk. 32 HMMA/warp/chunk.
//   LAYER 1: A = xh rows gathered via perm; out -> g_h1h (permuted, packed)
//   LAYER 2: A = g_h1h contiguous;          out -> fp32, scatter via perm
// ============================================================================
template <int LAYER>
__global__ __launch_bounds__(NTHREADS, 3)
void gemm_mma(const uint32_t* __restrict__ Ahg, const uint32_t* __restrict__ Whg,
              const float* __restrict__ bias, float* __restrict__ Out)
{
    const int tile = blockIdx.x;
    if (tile >= g_num_tiles) return;

    const int op        = g_tile_op[tile];
    const int row_start = g_tile_start[tile];
    const int nrows     = g_tile_rows[tile];
    const int col_base  = blockIdx.y * TN;
    const int tid       = threadIdx.x;
    const int lid       = tid & 31;
    const int wid       = tid >> 5;
    const int warp_m    = wid >> 1;    // 0..3  (32 rows each)
    const int warp_n    = wid & 1;     // 0..1  (32 cols each)
    const int g         = lid >> 2;    // 0..7
    const int tig       = lid & 3;     // 0..3

    extern __shared__ uint32_t smem[];
    const uint32_t sb = smem_u32(smem);

    // A cp.async: thread -> (row = tid>>1, q = tid&1); 2x16B per chunk
    const int arow = tid >> 1;
    const int aq   = tid & 1;
    const int arr  = (arow < nrows) ? arow : 0;
    const int asrc = (LAYER == 1) ? g_perm[row_start + arr] : (row_start + arr);
    const uint32_t* Aps = Ahg + (size_t)asrc * KPE + aq * 8;
    const uint32_t a_dst = (uint32_t)(arow * APITCH + aq * 8) * 4u;

    // B cp.async: thread -> (kp = tid>>4, n4 = tid&15); 1x16B per chunk
    const int bkp = tid >> 4;
    const int bn4 = tid & 15;
    const uint32_t* Bhs = Whg + ((size_t)op * KPE + bkp) * H_DIM + col_base + bn4 * 4;
    const uint32_t bh_dst = (uint32_t)(ST_BH + bkp * BPITCH + bn4 * 4) * 4u;

    auto issue = [&](int kc) {
        const uint32_t st = sb + (uint32_t)(kc % NSTAGE) * STAGE_BYTES;
        const uint32_t* as = Aps + kc * KPC;
        cp_async16(st + a_dst,      as);
        cp_async16(st + a_dst + 16, as + 4);
        cp_async16(st + bh_dst, Bhs + (size_t)kc * KPC * H_DIM);
    };

    float acc[2][4][4];
    #pragma unroll
    for (int mt = 0; mt < 2; mt++)
        #pragma unroll
        for (int nt = 0; nt < 4; nt++)
            #pragma unroll
            for (int e = 0; e < 4; e++) acc[mt][nt][e] = 0.f;

    // ---- prologue: stages 0..2 in flight ----
    issue(0); cp_commit();
    issue(1); cp_commit();
    issue(2); cp_commit();

    for (int kc = 0; kc < NCHUNK; kc++) {
        cp_wait<2>();      // groups through chunk kc complete
        __syncthreads();   // publish smem; all threads past compute of kc-1

        if (kc + 3 < NCHUNK) issue(kc + 3);
        cp_commit();       // commit every iter keeps group counts exact

        const uint32_t* st = smem + (kc % NSTAGE) * STAGE_U32;
        const uint32_t* Ah = st + ST_AH;
        const uint32_t* Bh = st + ST_BH;

        #pragma unroll
        for (int ks = 0; ks < 2; ks++) {
            const int k0 = ks * 8 + tig;
            const int k1 = k0 + 4;

            uint32_t bh[4][2];
            #pragma unroll
            for (int nt = 0; nt < 4; nt++) {
                const int c = warp_n * 32 + nt * 8 + g;
                bh[nt][0] = Bh[k0 * BPITCH + c];
                bh[nt][1] = Bh[k1 * BPITCH + c];
            }
            #pragma unroll
            for (int mt = 0; mt < 2; mt++) {
                const int m0 = warp_m * 32 + mt * 16 + g;
                uint32_t a0 = Ah[m0 * APITCH + k0];
                uint32_t a1 = Ah[(m0 + 8) * APITCH + k0];
                uint32_t a2 = Ah[m0 * APITCH + k1];
                uint32_t a3 = Ah[(m0 + 8) * APITCH + k1];
                #pragma unroll
                for (int nt = 0; nt < 4; nt++)
                    MMA(acc[mt][nt][0], acc[mt][nt][1], acc[mt][nt][2], acc[mt][nt][3],
                        a0, a1, a2, a3, bh[nt][0], bh[nt][1]);
            }
        }
    }

    // ---- epilogue ----
    float2 bb[4];
    #pragma unroll
    for (int nt = 0; nt < 4; nt++) {
        const int c = col_base + warp_n * 32 + nt * 8 + 2 * tig;
        bb[nt] = *(const float2*)(bias + (size_t)op * H_DIM + c);
    }
    #pragma unroll
    for (int mt = 0; mt < 2; mt++) {
        #pragma unroll
        for (int h = 0; h < 2; h++) {
            const int r = warp_m * 32 + mt * 16 + h * 8 + g;
            if (r < nrows) {
                if (LAYER == 1) {
                    // bias+relu, pack to f16 pairs in permuted order
                    const size_t rowbase = (size_t)(row_start + r) * KPE;
                    #pragma unroll
                    for (int nt = 0; nt < 4; nt++) {
                        const int kpc = col_base / 2 + warp_n * 16 + nt * 4 + tig;
                        float vx = fmaxf(acc[mt][nt][2 * h + 0] + bb[nt].x, 0.f);
                        float vy = fmaxf(acc[mt][nt][2 * h + 1] + bb[nt].y, 0.f);
                        g_h1h[rowbase + kpc] = pack2_f16(vx, vy);
                    }
                } else {
                    const int dst = g_perm[row_start + r];
                    float* orow = Out + (size_t)dst * H_DIM + col_base
                                      + warp_n * 32 + 2 * tig;
                    #pragma unroll
                    for (int nt = 0; nt < 4; nt++) {
                        float2 v;
                        v.x = fmaxf(acc[mt][nt][2 * h + 0] + bb[nt].x, 0.f);
                        v.y = fmaxf(acc[mt][nt][2 * h + 1] + bb[nt].y, 0.f);
                        *(float2*)(orow + nt * 8) = v;
                    }
                }
            }
        }
    }
}

// ============================================================================
// Launch
// ============================================================================
extern "C" void kernel_launch(void* const* d_in, const int* in_sizes, int n_in,
                              void* d_out, int out_size)
{
    const float* x      = (const float*)d_in[0];
    const int*   op_idx = (const int*)  d_in[1];
    const float* W1     = (const float*)d_in[2];
    const float* b1     = (const float*)d_in[3];
    const float* W2     = (const float*)d_in[4];
    const float* b2     = (const float*)d_in[5];
    float*       out    = (float*)d_out;
    (void)in_sizes; (void)n_in; (void)out_size;

    uint32_t *w1h, *w2h, *xh, *h1h;
    cudaGetSymbolAddress((void**)&w1h, g_w1h);
    cudaGetSymbolAddress((void**)&w2h, g_w2h);
    cudaGetSymbolAddress((void**)&xh,  g_xh);
    cudaGetSymbolAddress((void**)&h1h, g_h1h);

    cudaFuncSetAttribute(gemm_mma<1>, cudaFuncAttributeMaxDynamicSharedMemorySize, SMEM_NEED);
    cudaFuncSetAttribute(gemm_mma<2>, cudaFuncAttributeMaxDynamicSharedMemorySize, SMEM_NEED);

    setup_kernel<<<1, 512>>>(op_idx);
    convert_x_kernel<<<(B_DIM * KPE / 4) / NTHREADS, NTHREADS>>>(x, xh);
    convert_w_kernel<<<(O_DIM * KPE * 256) / NTHREADS, NTHREADS>>>(W1, w1h);
    convert_w_kernel<<<(O_DIM * KPE * 256) / NTHREADS, NTHREADS>>>(W2, w2h);

    dim3 grid(MAX_TILES, H_DIM / TN);
    gemm_mma<1><<<grid, NTHREADS, SMEM_NEED>>>(xh,  w1h, b1, nullptr);
    gemm_mma<2><<<grid, NTHREADS, SMEM_NEED>>>(h1h, w2h, b2, out);
}